// round 2
// baseline (speedup 1.0000x reference)
#include <cuda_runtime.h>
#include <cstdint>

#define D 256
#define LNUM 3
#define RNUM 4
#define NRXN 10
#define NMAX 100000
#define EMAX 400000
#define GMAX 2000
#define HCOLS 1280   // (R+1)*D : [W_self | W_rel0..3]
#define ENCD 768     // L*D
#define GCTX 778     // ENCD + NRXN
#define NCTX 1802    // ENCD + D + GCTX

// ---------------- scratch (device globals; no runtime allocation) ----------------
__device__ float d_X[(size_t)NMAX * D];          // current layer input (contiguous)
__device__ float d_H[(size_t)NMAX * HCOLS];      // GEMM output per layer
__device__ float d_Agg[(size_t)NMAX * D];        // edge aggregation
__device__ float d_Wcat[D * HCOLS];              // concatenated weights for one layer
__device__ float d_DegCnt[NMAX];
__device__ float d_InvDeg[NMAX];
__device__ float d_Gsum[(size_t)GMAX * ENCD];
__device__ int   d_Gcnt[GMAX];

// ---------------- small utility kernels ----------------
__global__ void k_zero_f(float* p, int n) {
    int i = blockIdx.x * blockDim.x + threadIdx.x;
    if (i < n) p[i] = 0.0f;
}
__global__ void k_zero_i(int* p, int n) {
    int i = blockIdx.x * blockDim.x + threadIdx.x;
    if (i < n) p[i] = 0;
}

// x0 = node_feature + flag_b + mask * flag_W[1];  also copy node_feature -> out cols [768:1024)
// center_mask arrives as int32 (harness materializes bool as int32)
__global__ void k_init(const float* __restrict__ nf, const float* __restrict__ flagW,
                       const float* __restrict__ flagb, const int* __restrict__ mask,
                       float* __restrict__ out_node, int n) {
    int i = blockIdx.x * blockDim.x + threadIdx.x;     // over n * (D/4)
    int total = n * (D / 4);
    if (i >= total) return;
    int node = i >> 6;          // D/4 = 64
    int c4   = i & 63;
    float4 v = reinterpret_cast<const float4*>(nf)[i];
    float4 b = reinterpret_cast<const float4*>(flagb)[c4];
    float  m = (mask[node] != 0) ? 1.0f : 0.0f;
    float4 w = reinterpret_cast<const float4*>(flagW + D)[c4];
    float4 x;
    x.x = v.x + b.x + m * w.x;
    x.y = v.y + b.y + m * w.y;
    x.z = v.z + b.z + m * w.z;
    x.w = v.w + b.w + m * w.w;
    reinterpret_cast<float4*>(d_X)[i] = x;
    // node_feature copy into node_context (rows only 8B aligned -> float2 stores)
    float* op = out_node + (size_t)node * NCTX + ENCD + (c4 << 2);
    reinterpret_cast<float2*>(op)[0] = make_float2(v.x, v.y);
    reinterpret_cast<float2*>(op)[1] = make_float2(v.z, v.w);
}

__global__ void k_deg(const int* __restrict__ dst, int e) {
    int i = blockIdx.x * blockDim.x + threadIdx.x;
    if (i < e) atomicAdd(&d_DegCnt[dst[i]], 1.0f);
}
__global__ void k_invdeg(int n) {
    int i = blockIdx.x * blockDim.x + threadIdx.x;
    if (i < n) d_InvDeg[i] = 1.0f / fmaxf(d_DegCnt[i], 1.0f);
}

// Build Wcat[k][j]: j<256 -> W_self[l][k][j]; else r=(j-256)>>8, e=(j-256)&255 -> W_rel[l][r][k][e]
__global__ void k_wcat(const float* __restrict__ Wself, const float* __restrict__ Wrel, int l) {
    int i = blockIdx.x * blockDim.x + threadIdx.x;     // D*HCOLS
    if (i >= D * HCOLS) return;
    int k = i / HCOLS, j = i % HCOLS;
    float v;
    if (j < D) {
        v = Wself[(size_t)l * D * D + k * D + j];
    } else {
        int r  = (j - D) >> 8;
        int ee = (j - D) & 255;
        v = Wrel[(((size_t)l * RNUM + r) * D + k) * (size_t)D + ee];
    }
    d_Wcat[i] = v;
}

// ---------------- SGEMM: C[M x 1280] = A[M x 256] * d_Wcat[256 x 1280] ----------------
__global__ __launch_bounds__(256, 2)
void k_sgemm(const float* __restrict__ A, float* __restrict__ C, int M) {
    const int K = 256;
    __shared__ float As[2][16][132];   // transposed A tile, padded
    __shared__ float Bs[2][16][128];

    const int tid  = threadIdx.x;
    const int brow = blockIdx.y * 128;
    const int bcol = blockIdx.x * 128;
    const int tx   = tid & 15;
    const int ty   = tid >> 4;

    float4 a_reg[2], b_reg[2];
    float  acc[8][8];
#pragma unroll
    for (int i = 0; i < 8; i++)
#pragma unroll
        for (int j = 0; j < 8; j++) acc[i][j] = 0.0f;

    // prologue: load tile 0
#pragma unroll
    for (int i = 0; i < 2; i++) {
        int f = tid + (i << 8);
        int ar = f >> 2, ak = (f & 3) << 2;
        int row = brow + ar;
        a_reg[i] = (row < M) ? *reinterpret_cast<const float4*>(A + (size_t)row * K + ak)
                             : make_float4(0.f, 0.f, 0.f, 0.f);
        int bk = f >> 5, bc = (f & 31) << 2;
        b_reg[i] = *reinterpret_cast<const float4*>(d_Wcat + bk * HCOLS + bcol + bc);
    }
#pragma unroll
    for (int i = 0; i < 2; i++) {
        int f = tid + (i << 8);
        int ar = f >> 2, ak = (f & 3) << 2;
        As[0][ak + 0][ar] = a_reg[i].x;
        As[0][ak + 1][ar] = a_reg[i].y;
        As[0][ak + 2][ar] = a_reg[i].z;
        As[0][ak + 3][ar] = a_reg[i].w;
        int bk = f >> 5, bc = (f & 31) << 2;
        *reinterpret_cast<float4*>(&Bs[0][bk][bc]) = b_reg[i];
    }
    __syncthreads();

#pragma unroll 1
    for (int kt = 0; kt < 16; kt++) {
        int cur = kt & 1;
        if (kt < 15) {
            int kof = (kt + 1) * 16;
#pragma unroll
            for (int i = 0; i < 2; i++) {
                int f = tid + (i << 8);
                int ar = f >> 2, ak = (f & 3) << 2;
                int row = brow + ar;
                a_reg[i] = (row < M) ? *reinterpret_cast<const float4*>(A + (size_t)row * K + kof + ak)
                                     : make_float4(0.f, 0.f, 0.f, 0.f);
                int bk = f >> 5, bc = (f & 31) << 2;
                b_reg[i] = *reinterpret_cast<const float4*>(d_Wcat + (kof + bk) * HCOLS + bcol + bc);
            }
        }
#pragma unroll
        for (int k = 0; k < 16; k++) {
            float a[8], b[8];
            *reinterpret_cast<float4*>(&a[0]) = *reinterpret_cast<const float4*>(&As[cur][k][ty * 8]);
            *reinterpret_cast<float4*>(&a[4]) = *reinterpret_cast<const float4*>(&As[cur][k][ty * 8 + 4]);
            *reinterpret_cast<float4*>(&b[0]) = *reinterpret_cast<const float4*>(&Bs[cur][k][tx * 8]);
            *reinterpret_cast<float4*>(&b[4]) = *reinterpret_cast<const float4*>(&Bs[cur][k][tx * 8 + 4]);
#pragma unroll
            for (int i = 0; i < 8; i++)
#pragma unroll
                for (int j = 0; j < 8; j++) acc[i][j] += a[i] * b[j];
        }
        if (kt < 15) {
            int nxt = cur ^ 1;
#pragma unroll
            for (int i = 0; i < 2; i++) {
                int f = tid + (i << 8);
                int ar = f >> 2, ak = (f & 3) << 2;
                As[nxt][ak + 0][ar] = a_reg[i].x;
                As[nxt][ak + 1][ar] = a_reg[i].y;
                As[nxt][ak + 2][ar] = a_reg[i].z;
                As[nxt][ak + 3][ar] = a_reg[i].w;
                int bk = f >> 5, bc = (f & 31) << 2;
                *reinterpret_cast<float4*>(&Bs[nxt][bk][bc]) = b_reg[i];
            }
            __syncthreads();
        }
    }

#pragma unroll
    for (int i = 0; i < 8; i++) {
        int row = brow + ty * 8 + i;
        if (row < M) {
            float* cp = C + (size_t)row * HCOLS + bcol + tx * 8;
            *reinterpret_cast<float4*>(cp)     = make_float4(acc[i][0], acc[i][1], acc[i][2], acc[i][3]);
            *reinterpret_cast<float4*>(cp + 4) = make_float4(acc[i][4], acc[i][5], acc[i][6], acc[i][7]);
        }
    }
}

// ---------------- edge gather + scatter-add ----------------
// thread i handles edge i>>6, float4 chunk q = i&63 of the 256-float message
__global__ void k_edge(const int* __restrict__ src, const int* __restrict__ dst,
                       const int* __restrict__ typ, int e) {
    int i = blockIdx.x * blockDim.x + threadIdx.x;
    if (i >= (e << 6)) return;
    int eid = i >> 6;
    int q   = i & 63;
    int s = src[eid], d2 = dst[eid], t = typ[eid];
    const float4 v = *reinterpret_cast<const float4*>(d_H + (size_t)s * HCOLS + D + t * D + (q << 2));
    float* ap = d_Agg + (size_t)d2 * D + (q << 2);
    atomicAdd(ap + 0, v.x);
    atomicAdd(ap + 1, v.y);
    atomicAdd(ap + 2, v.z);
    atomicAdd(ap + 3, v.w);
}

// xnew = relu(Hself + b_self + agg*invdeg) -> d_X and node_context cols [l*256, l*256+256)
__global__ void k_combine(const float* __restrict__ bself, float* __restrict__ out_node,
                          int l, int n) {
    int i = blockIdx.x * blockDim.x + threadIdx.x;   // n*(D/4)
    if (i >= n * (D / 4)) return;
    int node = i >> 6;
    int c4   = i & 63;
    float4 h = reinterpret_cast<const float4*>(d_H)[(size_t)node * (HCOLS / 4) + c4];
    float4 a = reinterpret_cast<const float4*>(d_Agg)[i];
    float4 b = reinterpret_cast<const float4*>(bself)[l * (D / 4) + c4];
    float id = d_InvDeg[node];
    float4 x;
    x.x = fmaxf(h.x + b.x + a.x * id, 0.0f);
    x.y = fmaxf(h.y + b.y + a.y * id, 0.0f);
    x.z = fmaxf(h.z + b.z + a.z * id, 0.0f);
    x.w = fmaxf(h.w + b.w + a.w * id, 0.0f);
    reinterpret_cast<float4*>(d_X)[i] = x;
    float* op = out_node + (size_t)node * NCTX + l * D + (c4 << 2);
    reinterpret_cast<float2*>(op)[0] = make_float2(x.x, x.y);
    reinterpret_cast<float2*>(op)[1] = make_float2(x.z, x.w);
}

// warp per node: sum node_enc (out cols [0:768)) into Gsum[batch[node]]
__global__ void k_pool(const int* __restrict__ batch, const float* __restrict__ out_node, int n) {
    int wid  = (blockIdx.x * blockDim.x + threadIdx.x) >> 5;
    int lane = threadIdx.x & 31;
    if (wid >= n) return;
    int g = batch[wid];
    if (lane == 0) atomicAdd(&d_Gcnt[g], 1);
    const float2* row = reinterpret_cast<const float2*>(out_node + (size_t)wid * NCTX);
    float* gs = d_Gsum + (size_t)g * ENCD;
#pragma unroll
    for (int j = lane; j < ENCD / 2; j += 32) {
        float2 v = row[j];
        atomicAdd(gs + 2 * j + 0, v.x);
        atomicAdd(gs + 2 * j + 1, v.y);
    }
}

// graph_context[g] = [Gsum/cnt (768) | onehot(reaction) (10)]
__global__ void k_graph(const int* __restrict__ reaction, float* __restrict__ gout, int g) {
    int i = blockIdx.x * blockDim.x + threadIdx.x;   // g * GCTX
    if (i >= g * GCTX) return;
    int gg = i / GCTX, c = i % GCTX;
    float v;
    if (c < ENCD) {
        v = d_Gsum[(size_t)gg * ENCD + c] / fmaxf((float)d_Gcnt[gg], 1.0f);
    } else {
        v = ((c - ENCD) == reaction[gg]) ? 1.0f : 0.0f;
    }
    gout[i] = v;
}

// node_context cols [1024:1802) = graph_context[batch[n]]
__global__ void k_bcast(const int* __restrict__ batch, const float* __restrict__ gout,
                        float* __restrict__ out_node, int n) {
    int i = blockIdx.x * blockDim.x + threadIdx.x;   // n * (GCTX/2)
    if (i >= n * (GCTX / 2)) return;
    int node = i / (GCTX / 2);
    int c2   = i % (GCTX / 2);
    float2 v = reinterpret_cast<const float2*>(gout + (size_t)batch[node] * GCTX)[c2];
    reinterpret_cast<float2*>(out_node + (size_t)node * NCTX + ENCD + D)[c2] = v;
}

// ---------------- host launcher ----------------
extern "C" void kernel_launch(void* const* d_in, const int* in_sizes, int n_in,
                              void* d_out, int out_size) {
    const float* node_feature = (const float*)d_in[0];
    const float* flag_W       = (const float*)d_in[1];
    const float* flag_b       = (const float*)d_in[2];
    const float* W_self       = (const float*)d_in[3];
    const float* b_self       = (const float*)d_in[4];
    const float* W_rel        = (const float*)d_in[5];
    const int*   edge_src     = (const int*)d_in[6];
    const int*   edge_dst     = (const int*)d_in[7];
    const int*   edge_type    = (const int*)d_in[8];
    const int*   batch        = (const int*)d_in[9];
    const int*   reaction     = (const int*)d_in[10];
    const int*   center_mask  = (const int*)d_in[11];   // bool materialized as int32

    const int n = in_sizes[9];    // batch has N entries
    const int e = in_sizes[6];    // edge_src has E entries
    const int g = in_sizes[10];   // reaction has G entries

    float* out  = (float*)d_out;
    float* gout = out + (size_t)n * NCTX;

    const int TPB = 256;
    auto blocks = [](long long total, int tpb) { return (int)((total + tpb - 1) / tpb); };

    // zero accumulators
    {
        float* degp; cudaGetSymbolAddress((void**)&degp, d_DegCnt);
        float* gsp;  cudaGetSymbolAddress((void**)&gsp,  d_Gsum);
        int*   gcp;  cudaGetSymbolAddress((void**)&gcp,  d_Gcnt);
        k_zero_f<<<blocks(n, TPB), TPB>>>(degp, n);
        k_zero_f<<<blocks((long long)g * ENCD, TPB), TPB>>>(gsp, g * ENCD);
        k_zero_i<<<blocks(g, TPB), TPB>>>(gcp, g);
    }

    // init x0 + node_feature copy
    k_init<<<blocks((long long)n * (D / 4), TPB), TPB>>>(node_feature, flag_W, flag_b,
                                                         center_mask, out, n);
    // degree
    k_deg<<<blocks(e, TPB), TPB>>>(edge_dst, e);
    k_invdeg<<<blocks(n, TPB), TPB>>>(n);

    float* aggp; cudaGetSymbolAddress((void**)&aggp, d_Agg);
    float* xp;   cudaGetSymbolAddress((void**)&xp, d_X);
    float* hp;   cudaGetSymbolAddress((void**)&hp, d_H);

    dim3 gemm_grid(HCOLS / 128, (n + 127) / 128);
    for (int l = 0; l < LNUM; l++) {
        k_wcat<<<blocks((long long)D * HCOLS, TPB), TPB>>>(W_self, W_rel, l);
        k_zero_f<<<blocks((long long)n * D, TPB), TPB>>>(aggp, n * D);
        k_sgemm<<<gemm_grid, 256>>>(xp, hp, n);
        k_edge<<<blocks((long long)e * 64, TPB), TPB>>>(edge_src, edge_dst, edge_type, e);
        k_combine<<<blocks((long long)n * (D / 4), TPB), TPB>>>(b_self, out, l, n);
    }

    // pooling + graph context + broadcast
    k_pool<<<blocks((long long)n * 32, TPB), TPB>>>(batch, out, n);
    k_graph<<<blocks((long long)g * GCTX, TPB), TPB>>>(reaction, gout, g);
    k_bcast<<<blocks((long long)n * (GCTX / 2), TPB), TPB>>>(batch, gout, out, n);
}

// round 4
// speedup vs baseline: 2.0190x; 2.0190x over previous
#include <cuda_runtime.h>
#include <cstdint>

#define D 256
#define LNUM 3
#define RNUM 4
#define NRXN 10
#define NMAX 100000
#define GMAX 2000
#define KDIM 1280    // [x(256) | S0..S3 (4*256)]
#define ENCD 768
#define GCTX 778
#define NCTX 1802

// ---------------- scratch ----------------
__device__ float d_XA[(size_t)NMAX * KDIM];
__device__ float d_XB[(size_t)NMAX * KDIM];
__device__ float d_Wbig[D * KDIM];   // [n][k] n-major (256 rows x 1280), tf32-rounded
__device__ float d_DegCnt[NMAX];
__device__ float d_InvDeg[NMAX];
__device__ float d_Gsum[(size_t)GMAX * ENCD];
__device__ int   d_Gcnt[GMAX];

// ---------------- helpers ----------------
__device__ __forceinline__ uint32_t smem_u32(const void* p) {
    uint32_t a;
    asm("{ .reg .u64 t; cvta.to.shared.u64 t, %1; cvt.u32.u64 %0, t; }" : "=r"(a) : "l"(p));
    return a;
}
__device__ __forceinline__ float tf32r(float x) {
    asm("cvt.rna.tf32.f32 %0, %1;" : "=f"(x) : "f"(x));
    return x;
}
__device__ __forceinline__ void mma8(float* c, const uint32_t* a, uint32_t b0, uint32_t b1) {
    asm volatile("mma.sync.aligned.m16n8k8.row.col.f32.tf32.tf32.f32 "
        "{%0,%1,%2,%3}, {%4,%5,%6,%7}, {%8,%9}, {%0,%1,%2,%3};"
        : "+f"(c[0]), "+f"(c[1]), "+f"(c[2]), "+f"(c[3])
        : "r"(a[0]), "r"(a[1]), "r"(a[2]), "r"(a[3]), "r"(b0), "r"(b1));
}
__device__ __forceinline__ void ldmx4(uint32_t* r, uint32_t addr) {
    asm volatile("ldmatrix.sync.aligned.m8n8.x4.shared.b16 {%0,%1,%2,%3}, [%4];"
        : "=r"(r[0]), "=r"(r[1]), "=r"(r[2]), "=r"(r[3]) : "r"(addr));
}

// ---------------- small kernels ----------------
__global__ void k_zero_f(float* p, long long n) {
    long long i = (long long)blockIdx.x * blockDim.x + threadIdx.x;
    if (i < n) p[i] = 0.0f;
}
__global__ void k_zero_i(int* p, int n) {
    int i = blockIdx.x * blockDim.x + threadIdx.x;
    if (i < n) p[i] = 0;
}
// zero the S region (cols 256..1280) of X
__global__ void k_zeroS(float* X, int n) {
    long long i = (long long)blockIdx.x * blockDim.x + threadIdx.x;   // n * 256 float4
    if (i >= (long long)n * 256) return;
    int node = (int)(i >> 8);
    int c4   = (int)(i & 255);
    reinterpret_cast<float4*>(X + (size_t)node * KDIM + D)[c4] = make_float4(0.f, 0.f, 0.f, 0.f);
}

// x0 = nf + flag_b + mask*flag_W[1] (tf32-rounded -> XA cols 0..255); nf copy -> out cols [768:1024)
__global__ void k_init(const float* __restrict__ nf, const float* __restrict__ flagW,
                       const float* __restrict__ flagb, const int* __restrict__ mask,
                       float* __restrict__ X, float* __restrict__ out_node, int n) {
    long long i = (long long)blockIdx.x * blockDim.x + threadIdx.x;
    if (i >= (long long)n * 64) return;
    int node = (int)(i >> 6);
    int c4   = (int)(i & 63);
    float4 v = reinterpret_cast<const float4*>(nf)[i];
    float4 b = reinterpret_cast<const float4*>(flagb)[c4];
    float  m = (mask[node] != 0) ? 1.0f : 0.0f;
    float4 w = reinterpret_cast<const float4*>(flagW + D)[c4];
    float4 x;
    x.x = tf32r(v.x + b.x + m * w.x);
    x.y = tf32r(v.y + b.y + m * w.y);
    x.z = tf32r(v.z + b.z + m * w.z);
    x.w = tf32r(v.w + b.w + m * w.w);
    reinterpret_cast<float4*>(X + (size_t)node * KDIM)[c4] = x;
    float* op = out_node + (size_t)node * NCTX + ENCD + (c4 << 2);
    reinterpret_cast<float2*>(op)[0] = make_float2(v.x, v.y);
    reinterpret_cast<float2*>(op)[1] = make_float2(v.z, v.w);
}

__global__ void k_deg(const int* __restrict__ dst, int e) {
    int i = blockIdx.x * blockDim.x + threadIdx.x;
    if (i < e) atomicAdd(&d_DegCnt[dst[i]], 1.0f);
}
__global__ void k_invdeg(int n) {
    int i = blockIdx.x * blockDim.x + threadIdx.x;
    if (i < n) d_InvDeg[i] = 1.0f / fmaxf(d_DegCnt[i], 1.0f);
}

// Wbig[n][k] (tf32-rounded): k<256 -> W_self[l][k][n]; else r=(k-256)>>8, kk=(k-256)&255 -> W_rel[l][r][kk][n]
__global__ void k_wcat(const float* __restrict__ Wself, const float* __restrict__ Wrel, int l) {
    int i = blockIdx.x * blockDim.x + threadIdx.x;     // D*KDIM, k fastest
    if (i >= D * KDIM) return;
    int n = i / KDIM, k = i % KDIM;
    float v;
    if (k < D) {
        v = Wself[(size_t)l * D * D + (size_t)k * D + n];
    } else {
        int r  = (k - D) >> 8;
        int kk = (k - D) & 255;
        v = Wrel[(((size_t)l * RNUM + r) * D + kk) * (size_t)D + n];
    }
    d_Wbig[i] = tf32r(v);
}

// ---------------- edge scatter: S[dst, t] += x[src] * invdeg[dst] ----------------
__global__ void k_edge(const int* __restrict__ src, const int* __restrict__ dst,
                       const int* __restrict__ typ, float* __restrict__ X, int e) {
    long long i = (long long)blockIdx.x * blockDim.x + threadIdx.x;
    if (i >= ((long long)e << 6)) return;
    int eid = (int)(i >> 6);
    int q   = (int)(i & 63);
    int s = src[eid], d2 = dst[eid], t = typ[eid];
    float id = d_InvDeg[d2];
    float4 v = *reinterpret_cast<const float4*>(X + (size_t)s * KDIM + (q << 2));
    float* ap = X + (size_t)d2 * KDIM + D + (t << 8) + (q << 2);
    atomicAdd(ap + 0, v.x * id);
    atomicAdd(ap + 1, v.y * id);
    atomicAdd(ap + 2, v.z * id);
    atomicAdd(ap + 3, v.w * id);
}

// ---------------- fused tf32 mma.sync GEMM ----------------
// C[M x 256] = relu(A[M x 1280] @ Wbig^T + bias); writes out cols [l*256,+256) and xnext (tf32)
#define BM 128
#define BN 256
#define KT 16
#define NKT (KDIM / KT)       // 80
#define ASTR 20               // row stride in floats (80B)
#define AS_FLOATS (BM * ASTR) // 2560
#define BS_FLOATS (BN * ASTR) // 5120
#define STG_FLOATS (AS_FLOATS + BS_FLOATS)  // 7680
#define GEMM_SMEM (3 * STG_FLOATS * 4)      // 92160 bytes

__global__ void __launch_bounds__(256, 1)
k_gemm(const float* __restrict__ A, const float* __restrict__ Wb,
       const float* __restrict__ bias, float* __restrict__ out_node,
       float* __restrict__ xnext, int l, int M)
{
    extern __shared__ float smem[];
    const int tid    = threadIdx.x;
    const int lane   = tid & 31;
    const int wid    = tid >> 5;
    const int warp_m = wid & 1;    // 2 x 64 rows
    const int warp_n = wid >> 1;   // 4 x 64 cols
    const int brow   = blockIdx.x * BM;
    const uint32_t sbase = smem_u32(smem);

    float acc[4][8][4];
#pragma unroll
    for (int a = 0; a < 4; a++)
#pragma unroll
        for (int b = 0; b < 8; b++)
#pragma unroll
            for (int c = 0; c < 4; c++) acc[a][b][c] = 0.0f;

    // ---- cp.async stage issue ----
    auto issue = [&](int kt) {
        const int buf = kt % 3;
        const uint32_t abase = sbase + buf * (STG_FLOATS * 4);
        const uint32_t bbase = abase + AS_FLOATS * 4;
        const int k0 = kt * KT;
#pragma unroll
        for (int i = 0; i < 2; i++) {           // A: 512 16B-chunks
            int j = tid + (i << 8);
            int row = j >> 2, c = j & 3;
            int gr = brow + row;
            const float* sp = A + (size_t)(gr < M ? gr : 0) * KDIM + k0 + (c << 2);
            uint32_t dp = abase + (row * ASTR + (c << 2)) * 4;
            uint32_t sz = (gr < M) ? 16u : 0u;
            asm volatile("cp.async.cg.shared.global [%0], [%1], 16, %2;"
                         :: "r"(dp), "l"(sp), "r"(sz));
        }
#pragma unroll
        for (int i = 0; i < 4; i++) {           // B: 1024 16B-chunks
            int j = tid + (i << 8);
            int row = j >> 2, c = j & 3;
            const float* sp = Wb + (size_t)row * KDIM + k0 + (c << 2);
            uint32_t dp = bbase + (row * ASTR + (c << 2)) * 4;
            asm volatile("cp.async.cg.shared.global [%0], [%1], 16;"
                         :: "r"(dp), "l"(sp));
        }
        asm volatile("cp.async.commit_group;");
    };

    issue(0);
    issue(1);

#pragma unroll 1
    for (int kt = 0; kt < NKT; kt++) {
        if (kt < NKT - 1) asm volatile("cp.async.wait_group 1;");
        else              asm volatile("cp.async.wait_group 0;");
        __syncthreads();
        if (kt + 2 < NKT) issue(kt + 2);

        const int buf = kt % 3;
        const uint32_t abase = sbase + buf * (STG_FLOATS * 4) + (warp_m * 64) * ASTR * 4;
        const uint32_t bbase = sbase + buf * (STG_FLOATS * 4) + AS_FLOATS * 4 + (warp_n * 64) * ASTR * 4;

        uint32_t breg[8][4];
#pragma unroll
        for (int n8 = 0; n8 < 8; n8++) {
            uint32_t addr = bbase + (((n8 << 3) + (lane & 7)) * ASTR + ((lane >> 3) << 2)) * 4;
            ldmx4(breg[n8], addr);
        }
#pragma unroll
        for (int h = 0; h < 2; h++) {
            uint32_t areg[4][4];
#pragma unroll
            for (int mt = 0; mt < 4; mt++) {
                uint32_t addr = abase + (((mt << 4) + (lane & 15)) * ASTR + (((h << 1) + (lane >> 4)) << 2)) * 4;
                ldmx4(areg[mt], addr);
            }
#pragma unroll
            for (int mt = 0; mt < 4; mt++)
#pragma unroll
                for (int n8 = 0; n8 < 8; n8++)
                    mma8(acc[mt][n8], areg[mt], breg[n8][(h << 1)], breg[n8][(h << 1) + 1]);
        }
    }

    // ---- epilogue: bias + relu, write out cols + xnext ----
#pragma unroll
    for (int mt = 0; mt < 4; mt++) {
        int r0 = brow + warp_m * 64 + (mt << 4) + (lane >> 2);
#pragma unroll
        for (int hf = 0; hf < 2; hf++) {
            int r = r0 + (hf << 3);
            if (r < M) {
#pragma unroll
                for (int n8 = 0; n8 < 8; n8++) {
                    int c = warp_n * 64 + (n8 << 3) + ((lane & 3) << 1);
                    float v0 = fmaxf(acc[mt][n8][(hf << 1) + 0] + bias[c], 0.0f);
                    float v1 = fmaxf(acc[mt][n8][(hf << 1) + 1] + bias[c + 1], 0.0f);
                    *reinterpret_cast<float2*>(out_node + (size_t)r * NCTX + l * D + c) =
                        make_float2(v0, v1);
                    if (xnext)
                        *reinterpret_cast<float2*>(xnext + (size_t)r * KDIM + c) =
                            make_float2(tf32r(v0), tf32r(v1));
                }
            }
        }
    }
}

// ---------------- pooling / context ----------------
__global__ void k_pool(const int* __restrict__ batch, const float* __restrict__ out_node, int n) {
    int wid  = (blockIdx.x * blockDim.x + threadIdx.x) >> 5;
    int lane = threadIdx.x & 31;
    if (wid >= n) return;
    int g = batch[wid];
    if (lane == 0) atomicAdd(&d_Gcnt[g], 1);
    const float2* row = reinterpret_cast<const float2*>(out_node + (size_t)wid * NCTX);
    float* gs = d_Gsum + (size_t)g * ENCD;
#pragma unroll
    for (int j = lane; j < ENCD / 2; j += 32) {
        float2 v = row[j];
        atomicAdd(gs + 2 * j + 0, v.x);
        atomicAdd(gs + 2 * j + 1, v.y);
    }
}

__global__ void k_graph(const int* __restrict__ reaction, float* __restrict__ gout, int g) {
    int i = blockIdx.x * blockDim.x + threadIdx.x;
    if (i >= g * GCTX) return;
    int gg = i / GCTX, c = i % GCTX;
    float v;
    if (c < ENCD) {
        v = d_Gsum[(size_t)gg * ENCD + c] / fmaxf((float)d_Gcnt[gg], 1.0f);
    } else {
        v = ((c - ENCD) == reaction[gg]) ? 1.0f : 0.0f;
    }
    gout[i] = v;
}

__global__ void k_bcast(const int* __restrict__ batch, const float* __restrict__ gout,
                        float* __restrict__ out_node, int n) {
    long long i = (long long)blockIdx.x * blockDim.x + threadIdx.x;
    if (i >= (long long)n * (GCTX / 2)) return;
    int node = (int)(i / (GCTX / 2));
    int c2   = (int)(i % (GCTX / 2));
    float2 v = reinterpret_cast<const float2*>(gout + (size_t)batch[node] * GCTX)[c2];
    reinterpret_cast<float2*>(out_node + (size_t)node * NCTX + ENCD + D)[c2] = v;
}

// ---------------- host launcher ----------------
extern "C" void kernel_launch(void* const* d_in, const int* in_sizes, int n_in,
                              void* d_out, int out_size) {
    const float* node_feature = (const float*)d_in[0];
    const float* flag_W       = (const float*)d_in[1];
    const float* flag_b       = (const float*)d_in[2];
    const float* W_self       = (const float*)d_in[3];
    const float* b_self       = (const float*)d_in[4];
    const float* W_rel        = (const float*)d_in[5];
    const int*   edge_src     = (const int*)d_in[6];
    const int*   edge_dst     = (const int*)d_in[7];
    const int*   edge_type    = (const int*)d_in[8];
    const int*   batch        = (const int*)d_in[9];
    const int*   reaction     = (const int*)d_in[10];
    const int*   center_mask  = (const int*)d_in[11];

    const int n = in_sizes[9];
    const int e = in_sizes[6];
    const int g = in_sizes[10];

    float* out  = (float*)d_out;
    float* gout = out + (size_t)n * NCTX;

    const int TPB = 256;
    auto blocks = [](long long total, int tpb) { return (unsigned)((total + tpb - 1) / tpb); };

    cudaFuncSetAttribute(k_gemm, cudaFuncAttributeMaxDynamicSharedMemorySize, GEMM_SMEM);

    float *xa, *xb, *wb, *degp, *gsp;
    int* gcp;
    cudaGetSymbolAddress((void**)&xa,   d_XA);
    cudaGetSymbolAddress((void**)&xb,   d_XB);
    cudaGetSymbolAddress((void**)&wb,   d_Wbig);
    cudaGetSymbolAddress((void**)&degp, d_DegCnt);
    cudaGetSymbolAddress((void**)&gsp,  d_Gsum);
    cudaGetSymbolAddress((void**)&gcp,  d_Gcnt);

    // zero accumulators
    k_zero_f<<<blocks(n, TPB), TPB>>>(degp, n);
    k_zero_f<<<blocks((long long)g * ENCD, TPB), TPB>>>(gsp, (long long)g * ENCD);
    k_zero_i<<<blocks(g, TPB), TPB>>>(gcp, g);

    // init x0 into XA, nf copy into out; zero S region of XA
    k_init<<<blocks((long long)n * 64, TPB), TPB>>>(node_feature, flag_W, flag_b,
                                                    center_mask, xa, out, n);
    k_zeroS<<<blocks((long long)n * 256, TPB), TPB>>>(xa, n);

    k_deg<<<blocks(e, TPB), TPB>>>(edge_dst, e);
    k_invdeg<<<blocks(n, TPB), TPB>>>(n);

    float* cur = xa;
    float* nxt = xb;
    const unsigned gemm_grid = blocks(n, BM);
    for (int l = 0; l < LNUM; l++) {
        k_wcat<<<blocks((long long)D * KDIM, TPB), TPB>>>(W_self, W_rel, l);
        k_edge<<<blocks((long long)e * 64, TPB), TPB>>>(edge_src, edge_dst, edge_type, cur, e);
        k_gemm<<<gemm_grid, 256, GEMM_SMEM>>>(cur, wb, b_self + (size_t)l * D, out,
                                              (l < LNUM - 1) ? nxt : nullptr, l, n);
        if (l < LNUM - 1) {
            k_zeroS<<<blocks((long long)n * 256, TPB), TPB>>>(nxt, n);
            float* t = cur; cur = nxt; nxt = t;
        }
    }

    k_pool<<<blocks((long long)n * 32, TPB), TPB>>>(batch, out, n);
    k_graph<<<blocks((long long)g * GCTX, TPB), TPB>>>(reaction, gout, g);
    k_bcast<<<blocks((long long)n * (GCTX / 2), TPB), TPB>>>(batch, gout, out, n);
}

// round 5
// speedup vs baseline: 2.3314x; 1.1547x over previous
#include <cuda_runtime.h>
#include <cstdint>

#define D 256
#define LNUM 3
#define RNUM 4
#define NRXN 10
#define NMAX 100000
#define GMAX 2000
#define KDIM 1280    // [x(256) | S0..S3 (4*256)]
#define ENCD 768
#define GCTX 778
#define NCTX 1802

// ---------------- scratch ----------------
__device__ float d_XA[(size_t)NMAX * KDIM];
__device__ float d_XB[(size_t)NMAX * KDIM];
__device__ float d_Wbig[D * KDIM];   // [n][k] n-major (256 rows x 1280), tf32-rounded
__device__ float d_DegCnt[NMAX];
__device__ float d_InvDeg[NMAX];

// ---------------- helpers ----------------
__device__ __forceinline__ uint32_t smem_u32(const void* p) {
    uint32_t a;
    asm("{ .reg .u64 t; cvta.to.shared.u64 t, %1; cvt.u32.u64 %0, t; }" : "=r"(a) : "l"(p));
    return a;
}
__device__ __forceinline__ float tf32r(float x) {
    asm("cvt.rna.tf32.f32 %0, %1;" : "=f"(x) : "f"(x));
    return x;
}
__device__ __forceinline__ void mma8(float* c, const uint32_t* a, uint32_t b0, uint32_t b1) {
    asm volatile("mma.sync.aligned.m16n8k8.row.col.f32.tf32.tf32.f32 "
        "{%0,%1,%2,%3}, {%4,%5,%6,%7}, {%8,%9}, {%0,%1,%2,%3};"
        : "+f"(c[0]), "+f"(c[1]), "+f"(c[2]), "+f"(c[3])
        : "r"(a[0]), "r"(a[1]), "r"(a[2]), "r"(a[3]), "r"(b0), "r"(b1));
}
__device__ __forceinline__ void ldmx4(uint32_t* r, uint32_t addr) {
    asm volatile("ldmatrix.sync.aligned.m8n8.x4.shared.b16 {%0,%1,%2,%3}, [%4];"
        : "=r"(r[0]), "=r"(r[1]), "=r"(r[2]), "=r"(r[3]) : "r"(addr));
}

// ---------------- small kernels ----------------
__global__ void k_zero_f(float* p, long long n) {
    long long i = (long long)blockIdx.x * blockDim.x + threadIdx.x;
    if (i < n) p[i] = 0.0f;
}

// x0 = nf + flag_b + mask*flag_W[1] (tf32 -> XA cols 0..255); zero S cols; nf copy -> out [768:1024)
__global__ void k_init(const float* __restrict__ nf, const float* __restrict__ flagW,
                       const float* __restrict__ flagb, const int* __restrict__ mask,
                       float* __restrict__ X, float* __restrict__ out_node, int n) {
    long long i = (long long)blockIdx.x * blockDim.x + threadIdx.x;
    if (i >= (long long)n * 64) return;
    int node = (int)(i >> 6);
    int c4   = (int)(i & 63);
    float4 v = reinterpret_cast<const float4*>(nf)[i];
    float4 b = reinterpret_cast<const float4*>(flagb)[c4];
    float  m = (mask[node] != 0) ? 1.0f : 0.0f;
    float4 w = reinterpret_cast<const float4*>(flagW + D)[c4];
    float4 x;
    x.x = tf32r(v.x + b.x + m * w.x);
    x.y = tf32r(v.y + b.y + m * w.y);
    x.z = tf32r(v.z + b.z + m * w.z);
    x.w = tf32r(v.w + b.w + m * w.w);
    reinterpret_cast<float4*>(X + (size_t)node * KDIM)[c4] = x;
    // zero S region: 4 float4 per thread (64 threads x 4 = 256 float4 = 1024 floats)
    float4 z = make_float4(0.f, 0.f, 0.f, 0.f);
    float4* sp = reinterpret_cast<float4*>(X + (size_t)node * KDIM + D) + (c4 << 2);
    sp[0] = z; sp[1] = z; sp[2] = z; sp[3] = z;
    float* op = out_node + (size_t)node * NCTX + ENCD + (c4 << 2);
    reinterpret_cast<float2*>(op)[0] = make_float2(v.x, v.y);
    reinterpret_cast<float2*>(op)[1] = make_float2(v.z, v.w);
}

__global__ void k_deg(const int* __restrict__ dst, int e) {
    int i = blockIdx.x * blockDim.x + threadIdx.x;
    if (i < e) atomicAdd(&d_DegCnt[dst[i]], 1.0f);
}
__global__ void k_invdeg(int n) {
    int i = blockIdx.x * blockDim.x + threadIdx.x;
    if (i < n) d_InvDeg[i] = 1.0f / fmaxf(d_DegCnt[i], 1.0f);
}

// Wbig[n][k] (tf32): k<256 -> W_self[l][k][n]; else r=(k-256)>>8, kk=(k-256)&255 -> W_rel[l][r][kk][n]
__global__ void k_wcat(const float* __restrict__ Wself, const float* __restrict__ Wrel, int l) {
    int i = blockIdx.x * blockDim.x + threadIdx.x;
    if (i >= D * KDIM) return;
    int n = i / KDIM, k = i % KDIM;
    float v;
    if (k < D) {
        v = Wself[(size_t)l * D * D + (size_t)k * D + n];
    } else {
        int r  = (k - D) >> 8;
        int kk = (k - D) & 255;
        v = Wrel[(((size_t)l * RNUM + r) * D + kk) * (size_t)D + n];
    }
    d_Wbig[i] = tf32r(v);
}

// ---------------- edge scatter: S[dst, t] += x[src] * invdeg[dst] (vector red) ----------------
__global__ void k_edge(const int* __restrict__ src, const int* __restrict__ dst,
                       const int* __restrict__ typ, float* __restrict__ X, int e) {
    long long i = (long long)blockIdx.x * blockDim.x + threadIdx.x;
    if (i >= ((long long)e << 6)) return;
    int eid = (int)(i >> 6);
    int q   = (int)(i & 63);
    int s = src[eid], d2 = dst[eid], t = typ[eid];
    float id = d_InvDeg[d2];
    float4 v = *reinterpret_cast<const float4*>(X + (size_t)s * KDIM + (q << 2));
    float* ap = X + (size_t)d2 * KDIM + D + (t << 8) + (q << 2);
    asm volatile("red.global.add.v4.f32 [%0], {%1, %2, %3, %4};"
                 :: "l"(ap), "f"(v.x * id), "f"(v.y * id), "f"(v.z * id), "f"(v.w * id)
                 : "memory");
}

// ---------------- fused tf32 mma.sync GEMM ----------------
// C[M x 256] = relu(A[M x 1280] @ Wbig^T + bias); writes out cols [l*256,+256) and xnext (tf32 + zeroed S)
#define BM 128
#define BN 256
#define KT 16
#define NKT (KDIM / KT)       // 80
#define ASTR 20               // row stride in floats (80B)
#define AS_FLOATS (BM * ASTR) // 2560
#define BS_FLOATS (BN * ASTR) // 5120
#define STG_FLOATS (AS_FLOATS + BS_FLOATS)  // 7680
#define GEMM_SMEM (3 * STG_FLOATS * 4)      // 92160 bytes

__global__ void __launch_bounds__(256, 1)
k_gemm(const float* __restrict__ A, const float* __restrict__ Wb,
       const float* __restrict__ bias, float* __restrict__ out_node,
       float* __restrict__ xnext, int l, int M)
{
    extern __shared__ float smem[];
    const int tid    = threadIdx.x;
    const int lane   = tid & 31;
    const int wid    = tid >> 5;
    const int warp_m = wid & 1;    // 2 x 64 rows
    const int warp_n = wid >> 1;   // 4 x 64 cols
    const int brow   = blockIdx.x * BM;
    const uint32_t sbase = smem_u32(smem);

    float acc[4][8][4];
#pragma unroll
    for (int a = 0; a < 4; a++)
#pragma unroll
        for (int b = 0; b < 8; b++)
#pragma unroll
            for (int c = 0; c < 4; c++) acc[a][b][c] = 0.0f;

    auto issue = [&](int kt) {
        const int buf = kt % 3;
        const uint32_t abase = sbase + buf * (STG_FLOATS * 4);
        const uint32_t bbase = abase + AS_FLOATS * 4;
        const int k0 = kt * KT;
#pragma unroll
        for (int i = 0; i < 2; i++) {
            int j = tid + (i << 8);
            int row = j >> 2, c = j & 3;
            int gr = brow + row;
            const float* sp = A + (size_t)(gr < M ? gr : 0) * KDIM + k0 + (c << 2);
            uint32_t dp = abase + (row * ASTR + (c << 2)) * 4;
            uint32_t sz = (gr < M) ? 16u : 0u;
            asm volatile("cp.async.cg.shared.global [%0], [%1], 16, %2;"
                         :: "r"(dp), "l"(sp), "r"(sz));
        }
#pragma unroll
        for (int i = 0; i < 4; i++) {
            int j = tid + (i << 8);
            int row = j >> 2, c = j & 3;
            const float* sp = Wb + (size_t)row * KDIM + k0 + (c << 2);
            uint32_t dp = bbase + (row * ASTR + (c << 2)) * 4;
            asm volatile("cp.async.cg.shared.global [%0], [%1], 16;"
                         :: "r"(dp), "l"(sp));
        }
        asm volatile("cp.async.commit_group;");
    };

    issue(0);
    issue(1);

#pragma unroll 1
    for (int kt = 0; kt < NKT; kt++) {
        if (kt < NKT - 1) asm volatile("cp.async.wait_group 1;");
        else              asm volatile("cp.async.wait_group 0;");
        __syncthreads();
        if (kt + 2 < NKT) issue(kt + 2);

        const int buf = kt % 3;
        const uint32_t abase = sbase + buf * (STG_FLOATS * 4) + (warp_m * 64) * ASTR * 4;
        const uint32_t bbase = sbase + buf * (STG_FLOATS * 4) + AS_FLOATS * 4 + (warp_n * 64) * ASTR * 4;

        uint32_t breg[8][4];
#pragma unroll
        for (int n8 = 0; n8 < 8; n8++) {
            uint32_t addr = bbase + (((n8 << 3) + (lane & 7)) * ASTR + ((lane >> 3) << 2)) * 4;
            ldmx4(breg[n8], addr);
        }
#pragma unroll
        for (int h = 0; h < 2; h++) {
            uint32_t areg[4][4];
#pragma unroll
            for (int mt = 0; mt < 4; mt++) {
                uint32_t addr = abase + (((mt << 4) + (lane & 15)) * ASTR + (((h << 1) + (lane >> 4)) << 2)) * 4;
                ldmx4(areg[mt], addr);
            }
#pragma unroll
            for (int mt = 0; mt < 4; mt++)
#pragma unroll
                for (int n8 = 0; n8 < 8; n8++)
                    mma8(acc[mt][n8], areg[mt], breg[n8][(h << 1)], breg[n8][(h << 1) + 1]);
        }
    }

    // ---- epilogue: bias + relu, write out cols + xnext; zero xnext S region ----
#pragma unroll
    for (int mt = 0; mt < 4; mt++) {
        int r0 = brow + warp_m * 64 + (mt << 4) + (lane >> 2);
#pragma unroll
        for (int hf = 0; hf < 2; hf++) {
            int r = r0 + (hf << 3);
            if (r < M) {
#pragma unroll
                for (int n8 = 0; n8 < 8; n8++) {
                    int c = warp_n * 64 + (n8 << 3) + ((lane & 3) << 1);
                    float v0 = fmaxf(acc[mt][n8][(hf << 1) + 0] + bias[c], 0.0f);
                    float v1 = fmaxf(acc[mt][n8][(hf << 1) + 1] + bias[c + 1], 0.0f);
                    *reinterpret_cast<float2*>(out_node + (size_t)r * NCTX + l * D + c) =
                        make_float2(v0, v1);
                    if (xnext)
                        *reinterpret_cast<float2*>(xnext + (size_t)r * KDIM + c) =
                            make_float2(tf32r(v0), tf32r(v1));
                }
            }
        }
    }
    if (xnext) {
        const float4 z = make_float4(0.f, 0.f, 0.f, 0.f);
#pragma unroll 1
        for (int idx = tid; idx < BM * 256; idx += 256) {
            int row = idx >> 8;
            int c4  = idx & 255;
            int r = brow + row;
            if (r < M)
                reinterpret_cast<float4*>(xnext + (size_t)r * KDIM + D)[c4] = z;
        }
    }
}

// ---------------- pooling: one block per graph (batch sorted), no atomics ----------------
__global__ void __launch_bounds__(256)
k_pool(const int* __restrict__ batch, const int* __restrict__ reaction,
       const float* __restrict__ out_node, float* __restrict__ gout, int n) {
    const int gg  = blockIdx.x;
    const int tid = threadIdx.x;
    // lower/upper bound binary search over sorted batch
    int lo = 0, hi = n;
    while (lo < hi) { int m = (lo + hi) >> 1; if (batch[m] < gg) lo = m + 1; else hi = m; }
    const int s = lo;
    hi = n;
    while (lo < hi) { int m = (lo + hi) >> 1; if (batch[m] <= gg) lo = m + 1; else hi = m; }
    const int e2 = lo;
    const float inv = 1.0f / fmaxf((float)(e2 - s), 1.0f);
    float a0 = 0.f, a1 = 0.f, a2 = 0.f;
    for (int node = s; node < e2; node++) {
        const float* row = out_node + (size_t)node * NCTX;
        a0 += row[tid];
        a1 += row[tid + 256];
        a2 += row[tid + 512];
    }
    float* gp = gout + (size_t)gg * GCTX;
    gp[tid]       = a0 * inv;
    gp[tid + 256] = a1 * inv;
    gp[tid + 512] = a2 * inv;
    if (tid < NRXN) gp[ENCD + tid] = (tid == reaction[gg]) ? 1.0f : 0.0f;
}

__global__ void k_bcast(const int* __restrict__ batch, const float* __restrict__ gout,
                        float* __restrict__ out_node, int n) {
    long long i = (long long)blockIdx.x * blockDim.x + threadIdx.x;
    if (i >= (long long)n * (GCTX / 2)) return;
    int node = (int)(i / (GCTX / 2));
    int c2   = (int)(i % (GCTX / 2));
    float2 v = reinterpret_cast<const float2*>(gout + (size_t)batch[node] * GCTX)[c2];
    reinterpret_cast<float2*>(out_node + (size_t)node * NCTX + ENCD + D)[c2] = v;
}

// ---------------- host launcher ----------------
extern "C" void kernel_launch(void* const* d_in, const int* in_sizes, int n_in,
                              void* d_out, int out_size) {
    const float* node_feature = (const float*)d_in[0];
    const float* flag_W       = (const float*)d_in[1];
    const float* flag_b       = (const float*)d_in[2];
    const float* W_self       = (const float*)d_in[3];
    const float* b_self       = (const float*)d_in[4];
    const float* W_rel        = (const float*)d_in[5];
    const int*   edge_src     = (const int*)d_in[6];
    const int*   edge_dst     = (const int*)d_in[7];
    const int*   edge_type    = (const int*)d_in[8];
    const int*   batch        = (const int*)d_in[9];
    const int*   reaction     = (const int*)d_in[10];
    const int*   center_mask  = (const int*)d_in[11];

    const int n = in_sizes[9];
    const int e = in_sizes[6];
    const int g = in_sizes[10];

    float* out  = (float*)d_out;
    float* gout = out + (size_t)n * NCTX;

    const int TPB = 256;
    auto blocks = [](long long total, int tpb) { return (unsigned)((total + tpb - 1) / tpb); };

    cudaFuncSetAttribute(k_gemm, cudaFuncAttributeMaxDynamicSharedMemorySize, GEMM_SMEM);

    float *xa, *xb, *wb, *degp;
    cudaGetSymbolAddress((void**)&xa,   d_XA);
    cudaGetSymbolAddress((void**)&xb,   d_XB);
    cudaGetSymbolAddress((void**)&wb,   d_Wbig);
    cudaGetSymbolAddress((void**)&degp, d_DegCnt);

    k_zero_f<<<blocks(n, TPB), TPB>>>(degp, n);

    k_init<<<blocks((long long)n * 64, TPB), TPB>>>(node_feature, flag_W, flag_b,
                                                    center_mask, xa, out, n);
    k_deg<<<blocks(e, TPB), TPB>>>(edge_dst, e);
    k_invdeg<<<blocks(n, TPB), TPB>>>(n);

    float* cur = xa;
    float* nxt = xb;
    const unsigned gemm_grid = blocks(n, BM);
    for (int l = 0; l < LNUM; l++) {
        k_wcat<<<blocks((long long)D * KDIM, TPB), TPB>>>(W_self, W_rel, l);
        k_edge<<<blocks((long long)e * 64, TPB), TPB>>>(edge_src, edge_dst, edge_type, cur, e);
        k_gemm<<<gemm_grid, 256, GEMM_SMEM>>>(cur, wb, b_self + (size_t)l * D, out,
                                              (l < LNUM - 1) ? nxt : nullptr, l, n);
        if (l < LNUM - 1) { float* t = cur; cur = nxt; nxt = t; }
    }

    k_pool<<<g, 256>>>(batch, reaction, out, gout, n);
    k_bcast<<<blocks((long long)n * (GCTX / 2), TPB), TPB>>>(batch, gout, out, n);
}